// round 7
// baseline (speedup 1.0000x reference)
#include <cuda_runtime.h>
#include <cstdint>

#define BB 2048
#define NN 512
#define UU 64
#define NT 1024          // threads per CTA (32 warps)
#define NCTA 128         // persistent CTAs
#define BPC (BB / NCTA)  // 16 batches per CTA

#define TILE_F 32768     // 512*64 floats = 128 KB
// tile + arrA + arrB + ksm + rpart + scratch + knp
#define SMEM_FLOATS (TILE_F + NN + NN + UU + 4096 + 32 + 8)

__device__ __forceinline__ void cp_async16(float* smem_dst, const float* gsrc) {
    uint32_t sa = (uint32_t)__cvta_generic_to_shared(smem_dst);
    asm volatile("cp.async.cg.shared.global [%0], [%1], 16;" :: "r"(sa), "l"(gsrc));
}

// block sum over 1024 threads (32 warps); 2 barriers
__device__ __forceinline__ float blockReduceSum(float v, float* scratch) {
    #pragma unroll
    for (int o = 16; o; o >>= 1) v += __shfl_xor_sync(0xffffffffu, v, o);
    int w = threadIdx.x >> 5, l = threadIdx.x & 31;
    if (l == 0) scratch[w] = v;
    __syncthreads();
    if (threadIdx.x < 32) {
        v = scratch[threadIdx.x];
        #pragma unroll
        for (int o = 16; o; o >>= 1) v += __shfl_xor_sync(0xffffffffu, v, o);
        if (threadIdx.x == 0) scratch[0] = v;
    }
    __syncthreads();
    v = scratch[0];
    return v;   // all threads read scratch[0]; next write to scratch is behind another barrier
}

__global__ __launch_bounds__(NT, 1) void ntm_kernel(
    const float* __restrict__ memory, const float* __restrict__ k,
    const float* __restrict__ beta_p, const float* __restrict__ g_p,
    const float* __restrict__ s,      const float* __restrict__ gamma_p,
    const float* __restrict__ w_pre,  const float* __restrict__ e,
    const float* __restrict__ a,
    float* __restrict__ out_w, float* __restrict__ out_r, float* __restrict__ out_m)
{
    extern __shared__ float dyn[];
    float* tile    = dyn;                  // 32768
    float* arrA    = dyn + TILE_F;         // 512: sims -> final w
    float* arrB    = arrA + NN;            // 512: gated weights / r stage-2
    float* ksm     = arrB + NN;            // 64
    float* rpart   = ksm + UU;             // 4096
    float* scratch = rpart + 4096;         // 32
    float* knp     = scratch + 32;         // 1: 1/||k||

    const int tid  = threadIdx.x;
    const int gid  = tid >> 4;             // 0..63
    const int gl   = tid & 15;
    const int warp = tid >> 5;
    const int lane = tid & 31;

    const float beta  = beta_p[0];
    const float gg    = g_p[0];
    const float gamma = gamma_p[0];

    const int b0 = blockIdx.x * BPC;

    // ---- prologue: issue all 4 quarters of batch b0 ----
    {
        const float* memb = memory + ((long)b0 << 15);
        #pragma unroll
        for (int j = 0; j < 4; ++j) {
            int q1 = j * 2048 + tid;              // float4 index
            cp_async16(tile + q1 * 4, memb + q1 * 4);
            int q2 = q1 + 1024;
            cp_async16(tile + q2 * 4, memb + q2 * 4);
            asm volatile("cp.async.commit_group;");
        }
    }

    for (int i = 0; i < BPC; ++i) {
        const int b = b0 + i;
        float* outmb = out_m + ((long)b << 15);
        const float s0 = s[b * 3 + 0], s1 = s[b * 3 + 1], s2 = s[b * 3 + 2];

        // ---- k vector + 1/||k|| (warp 0), overlaps in-flight loads ----
        if (tid < UU) ksm[tid] = k[b * UU + tid];
        if (warp == 0) {
            float kv0 = k[b * UU + lane];
            float kv1 = k[b * UU + 32 + lane];
            float kq = kv0 * kv0 + kv1 * kv1;
            #pragma unroll
            for (int o = 16; o; o >>= 1) kq += __shfl_xor_sync(0xffffffffu, kq, o);
            if (lane == 0) knp[0] = 1.f / fmaxf(sqrtf(kq), 1e-8f);
        }
        __syncthreads();                      // publish ksm, knp
        const float4 k4 = *(const float4*)&ksm[gl * 4];

        // ---- phase 1: sims; each thread reads only its own cp.async data ----
        #pragma unroll
        for (int j = 0; j < 4; ++j) {
            if      (j == 0) asm volatile("cp.async.wait_group 3;");
            else if (j == 1) asm volatile("cp.async.wait_group 2;");
            else if (j == 2) asm volatile("cp.async.wait_group 1;");
            else             asm volatile("cp.async.wait_group 0;");
            #pragma unroll
            for (int h = 0; h < 2; ++h) {
                int row = j * 128 + h * 64 + gid;
                float4 m = *(const float4*)(tile + row * 64 + gl * 4);
                float d = m.x * k4.x + m.y * k4.y + m.z * k4.z + m.w * k4.w;
                float q = m.x * m.x + m.y * m.y + m.z * m.z + m.w * m.w;
                #pragma unroll
                for (int o = 8; o; o >>= 1) {
                    d += __shfl_xor_sync(0xffffffffu, d, o);
                    q += __shfl_xor_sync(0xffffffffu, q, o);
                }
                if (gl == 0) arrA[row] = d / fmaxf(sqrtf(q), 1e-8f);  // d/nx (ny deferred)
            }
        }
        __syncthreads();                      // publish arrA (d/nx)

        // ---- phase 2: softmax (no max-sub; |beta*sim|<=beta), gate, shift, sharpen ----
        const float bn = beta * knp[0];
        float e0 = (tid < NN) ? expf(bn * arrA[tid]) : 0.f;
        float esum = blockReduceSum(e0, scratch);
        float einv = 1.f / esum;
        if (tid < NN)
            arrB[tid] = gg * e0 * einv + (1.f - gg) * w_pre[b * NN + tid];
        __syncthreads();                      // publish arrB

        float p0 = 0.f;
        if (tid < NN) {
            float ws = s0 * arrB[(tid + 511) & 511] + s1 * arrB[tid]
                     + s2 * arrB[(tid + 1) & 511];
            p0 = exp2f(gamma * log2f(ws));    // ws > 0
        }
        float psum = blockReduceSum(p0, scratch);
        float pinv = 1.f / psum;
        if (tid < NN) {
            float w0 = p0 * pinv + 1e-16f;
            arrA[tid] = w0;
            out_w[b * NN + tid] = w0;
        }
        __syncthreads();                      // publish w

        // ---- phase 3: read tile + erase/add store + recycle quarters (NO barriers) ----
        const float4 e4 = *(const float4*)(e + b * UU + gl * 4);
        const float4 a4 = *(const float4*)(a + b * UU + gl * 4);
        const bool more = (i + 1 < BPC);
        const float* nmemb = memory + ((long)(b + 1) << 15);  // only deref'd if more
        float4 racc = make_float4(0.f, 0.f, 0.f, 0.f);
        #pragma unroll
        for (int j = 0; j < 4; ++j) {
            #pragma unroll
            for (int h = 0; h < 2; ++h) {
                int row = j * 128 + h * 64 + gid;
                float4 m = *(const float4*)(tile + row * 64 + gl * 4);
                float wn = arrA[row];
                racc.x += wn * m.x;
                racc.y += wn * m.y;
                racc.z += wn * m.z;
                racc.w += wn * m.w;
                float4 nm;
                nm.x = m.x * (1.f - wn * e4.x) + wn * a4.x;
                nm.y = m.y * (1.f - wn * e4.y) + wn * a4.y;
                nm.z = m.z * (1.f - wn * e4.z) + wn * a4.z;
                nm.w = m.w * (1.f - wn * e4.w) + wn * a4.w;
                *(float4*)(outmb + row * 64 + gl * 4) = nm;
                // this thread is done with this tile float4 -> safe to recycle below
                if (more) {
                    int qi = j * 2048 + h * 1024 + tid;   // == row*16 + gl
                    cp_async16(tile + qi * 4, nmemb + qi * 4);
                }
            }
            asm volatile("cp.async.commit_group;");       // 4 groups/batch (empty ok on last)
        }

        // ---- r epilogue ----
        *(float4*)&rpart[gid * 64 + gl * 4] = racc;
        __syncthreads();
        if (tid < 512) {
            int col = tid & 63, hh = tid >> 6;
            float sv = 0.f;
            #pragma unroll
            for (int r2 = 0; r2 < 8; ++r2) sv += rpart[(hh * 8 + r2) * 64 + col];
            arrB[hh * 64 + col] = sv;
        }
        __syncthreads();
        if (tid < UU) {
            float rs = 0.f;
            #pragma unroll
            for (int i2 = 0; i2 < 8; ++i2) rs += arrB[i2 * 64 + tid];
            out_r[b * UU + tid] = rs;
        }
        __syncthreads();   // protect arrB/knp/ksm from next-batch writers
    }
}

extern "C" void kernel_launch(void* const* d_in, const int* in_sizes, int n_in,
                              void* d_out, int out_size) {
    const float* memory = (const float*)d_in[0];
    const float* k      = (const float*)d_in[1];
    const float* beta   = (const float*)d_in[2];
    const float* g      = (const float*)d_in[3];
    const float* s      = (const float*)d_in[4];
    const float* gamma  = (const float*)d_in[5];
    const float* w_pre  = (const float*)d_in[6];
    const float* e      = (const float*)d_in[7];
    const float* a      = (const float*)d_in[8];

    float* out   = (float*)d_out;
    float* out_w = out;                               // (B, N)
    float* out_r = out_w + (long)BB * NN;             // (B, U)
    float* out_m = out_r + (long)BB * UU;             // (B, N, U)

    const int smem_bytes = SMEM_FLOATS * sizeof(float);
    cudaFuncSetAttribute(ntm_kernel,
                         cudaFuncAttributeMaxDynamicSharedMemorySize,
                         smem_bytes);

    ntm_kernel<<<NCTA, NT, smem_bytes>>>(memory, k, beta, g, s, gamma, w_pre, e, a,
                                         out_w, out_r, out_m);
}